// round 5
// baseline (speedup 1.0000x reference)
#include <cuda_runtime.h>
#include <cstdint>

// NonLocalMeansSmoothing: x [8,256,256,8] fp32 -> same. K=5, sigma=1, h=1.
//
// w ∝ exp(-(||c-n||^2 + 0.5*(di^2+dj^2)))   (gaussian global norm cancels)
// Augmented-dot formulation: site v = (√2·n[8], 1, ||n||^2)  (5 f32x2 regs),
// center u = log2e·(√2·c[8], -||c||^2, -1)  ⇒  u·v = log2e(2c·n - ||c||^2 - ||n||^2).
// exponent = u·v + cg(di,dj);  w = 2^exponent.
// Accumulating w·v also yields Σw in the 9th lane for free.
// 2 vertical pixels/thread: 30 site-loads serve 50 taps.

#define BATCH 8
#define NX 256
#define NY 256
#define TILE 32
#define HALO 2
#define SMW (TILE + 2 * HALO)   // 36
#define L2E 1.4426950408889634f
#define SQ2 1.4142135623730951f

typedef unsigned long long u64;

__device__ __forceinline__ u64 fma2(u64 a, u64 b, u64 c) {
    u64 d; asm("fma.rn.f32x2 %0,%1,%2,%3;" : "=l"(d) : "l"(a), "l"(b), "l"(c)); return d;
}
__device__ __forceinline__ u64 mul2(u64 a, u64 b) {
    u64 d; asm("mul.rn.f32x2 %0,%1,%2;" : "=l"(d) : "l"(a), "l"(b)); return d;
}
__device__ __forceinline__ u64 pack2(float lo, float hi) {
    u64 d; asm("mov.b64 %0,{%1,%2};" : "=l"(d) : "f"(lo), "f"(hi)); return d;
}
__device__ __forceinline__ float hadd2(u64 a) {
    float lo, hi; asm("mov.b64 {%0,%1},%2;" : "=f"(lo), "=f"(hi) : "l"(a));
    return lo + hi;
}
__device__ __forceinline__ float lo2(u64 a) {
    float lo, hi; asm("mov.b64 {%0,%1},%2;" : "=f"(lo), "=f"(hi) : "l"(a));
    return lo;
}
__device__ __forceinline__ float ex2f(float x) {
    float r; asm("ex2.approx.ftz.f32 %0,%1;" : "=f"(r) : "f"(x)); return r;
}
__device__ __forceinline__ int refl(int p, int n) {
    if (p < 0) p = -p;
    if (p >= n) p = 2 * n - 2 - p;
    return p;
}

__global__ __launch_bounds__(512, 2)
void nlm_kernel(const float* __restrict__ x, float* __restrict__ out) {
    __shared__ ulonglong2 S01[SMW * SMW];  // (√2x0,√2x1),(√2x2,√2x3)
    __shared__ ulonglong2 S23[SMW * SMW];  // (√2x4,√2x5),(√2x6,√2x7)
    __shared__ u64        S4[SMW * SMW];   // (1, ||x||^2)

    const int b   = blockIdx.z;
    const int ti0 = blockIdx.y * TILE;
    const int tj0 = blockIdx.x * TILE;
    const int tid = threadIdx.y * 32 + threadIdx.x;

    const float* xb = x + (size_t)b * NX * NY * 8;

    // Halo load: 1296 sites / 512 threads.
    for (int p = tid; p < SMW * SMW; p += 512) {
        int r = p / SMW;
        int c = p - r * SMW;
        int gi = refl(ti0 + r - HALO, NX);
        int gj = refl(tj0 + c - HALO, NY);
        const float4* src = reinterpret_cast<const float4*>(
            xb + ((size_t)gi * NY + gj) * 8);
        float4 v0 = src[0];
        float4 v1 = src[1];
        float nrm = v0.x * v0.x + v0.y * v0.y + v0.z * v0.z + v0.w * v0.w
                  + v1.x * v1.x + v1.y * v1.y + v1.z * v1.z + v1.w * v1.w;
        ulonglong2 a, bb;
        a.x  = pack2(SQ2 * v0.x, SQ2 * v0.y);
        a.y  = pack2(SQ2 * v0.z, SQ2 * v0.w);
        bb.x = pack2(SQ2 * v1.x, SQ2 * v1.y);
        bb.y = pack2(SQ2 * v1.z, SQ2 * v1.w);
        S01[p] = a;
        S23[p] = bb;
        S4[p]  = pack2(1.0f, nrm);
    }
    __syncthreads();

    // Two vertically adjacent pixels per thread.
    const int y0  = 2 * threadIdx.y;      // tile-local row of pixel0
    const int lj  = threadIdx.x + HALO;

    const u64 l2e2 = pack2(L2E, L2E);

    // Build centers u = L2E*(√2c, -||c||^2, -1) from stored site records.
    u64 U0[5], U1[5];
    {
        int k0 = (y0 + HALO) * SMW + lj;
        ulonglong2 a = S01[k0], c2 = S23[k0];
        U0[0] = mul2(l2e2, a.x);  U0[1] = mul2(l2e2, a.y);
        U0[2] = mul2(l2e2, c2.x); U0[3] = mul2(l2e2, c2.y);
        float nrm = hadd2(S4[k0]) - 1.0f;   // hi lane is ||c||^2; lo is 1
        U0[4] = pack2(-L2E * nrm, -L2E);
        int k1 = k0 + SMW;
        ulonglong2 a1 = S01[k1], c3 = S23[k1];
        U1[0] = mul2(l2e2, a1.x);  U1[1] = mul2(l2e2, a1.y);
        U1[2] = mul2(l2e2, c3.x);  U1[3] = mul2(l2e2, c3.y);
        float nrm1 = hadd2(S4[k1]) - 1.0f;
        U1[4] = pack2(-L2E * nrm1, -L2E);
    }

    u64 acc0[5] = {0, 0, 0, 0, 0};
    u64 acc1[5] = {0, 0, 0, 0, 0};

    // Window rows r = 0..5 (smem rows y0+r). pixel0: r in [0,4]; pixel1: r in [1,5].
#pragma unroll
    for (int r = 0; r < 6; r++) {
#pragma unroll
        for (int dj = -HALO; dj <= HALO; dj++) {
            const int k = (y0 + r) * SMW + (lj + dj);
            const ulonglong2 N01 = S01[k];
            const ulonglong2 N23 = S23[k];
            const u64        N4  = S4[k];

            if (r <= 4) {
                const int di = r - 2;
                const float cg = -L2E * (0.5f * (float)(di * di + dj * dj));
                u64 dp = mul2(U0[0], N01.x);
                dp = fma2(U0[1], N01.y, dp);
                dp = fma2(U0[2], N23.x, dp);
                dp = fma2(U0[3], N23.y, dp);
                dp = fma2(U0[4], N4,    dp);
                const float w = ex2f(hadd2(dp) + cg);
                const u64 w2 = pack2(w, w);
                acc0[0] = fma2(w2, N01.x, acc0[0]);
                acc0[1] = fma2(w2, N01.y, acc0[1]);
                acc0[2] = fma2(w2, N23.x, acc0[2]);
                acc0[3] = fma2(w2, N23.y, acc0[3]);
                acc0[4] = fma2(w2, N4,    acc0[4]);   // lo lane: Σw
            }
            if (r >= 1) {
                const int di = r - 3;
                const float cg = -L2E * (0.5f * (float)(di * di + dj * dj));
                u64 dp = mul2(U1[0], N01.x);
                dp = fma2(U1[1], N01.y, dp);
                dp = fma2(U1[2], N23.x, dp);
                dp = fma2(U1[3], N23.y, dp);
                dp = fma2(U1[4], N4,    dp);
                const float w = ex2f(hadd2(dp) + cg);
                const u64 w2 = pack2(w, w);
                acc1[0] = fma2(w2, N01.x, acc1[0]);
                acc1[1] = fma2(w2, N01.y, acc1[1]);
                acc1[2] = fma2(w2, N23.x, acc1[2]);
                acc1[3] = fma2(w2, N23.y, acc1[3]);
                acc1[4] = fma2(w2, N4,    acc1[4]);
            }
        }
    }

    const int gi0 = ti0 + y0;
    const int gj  = tj0 + threadIdx.x;

    {
        // acc holds Σw·√2·n ; divide by √2·Σw.
        const float inv = __fdividef(0.70710678118654752f, lo2(acc0[4]));
        const u64 inv2 = pack2(inv, inv);
        ulonglong2 r0, r1;
        r0.x = mul2(acc0[0], inv2); r0.y = mul2(acc0[1], inv2);
        r1.x = mul2(acc0[2], inv2); r1.y = mul2(acc0[3], inv2);
        ulonglong2* dst = reinterpret_cast<ulonglong2*>(
            out + (((size_t)b * NX + gi0) * NY + gj) * 8);
        dst[0] = r0; dst[1] = r1;
    }
    {
        const float inv = __fdividef(0.70710678118654752f, lo2(acc1[4]));
        const u64 inv2 = pack2(inv, inv);
        ulonglong2 r0, r1;
        r0.x = mul2(acc1[0], inv2); r0.y = mul2(acc1[1], inv2);
        r1.x = mul2(acc1[2], inv2); r1.y = mul2(acc1[3], inv2);
        ulonglong2* dst = reinterpret_cast<ulonglong2*>(
            out + (((size_t)b * NX + gi0 + 1) * NY + gj) * 8);
        dst[0] = r0; dst[1] = r1;
    }
}

extern "C" void kernel_launch(void* const* d_in, const int* in_sizes, int n_in,
                              void* d_out, int out_size) {
    const float* x = (const float*)d_in[0];
    float* out = (float*)d_out;
    dim3 block(32, 16, 1);
    dim3 grid(NY / TILE, NX / TILE, BATCH);  // (8, 8, 8)
    nlm_kernel<<<grid, block>>>(x, out);
}

// round 6
// speedup vs baseline: 1.0850x; 1.0850x over previous
#include <cuda_runtime.h>
#include <cstdint>

// NonLocalMeansSmoothing: x [8,256,256,8] fp32 -> same. K=5, sigma=1, h=1.
// w ∝ exp(-(||c-n||^2 + 0.5*(di^2+dj^2)))  (gaussian global norm cancels)
// ||c-n||^2 = ||c||^2 + ||n||^2 - 2 c·n, norms pre-scaled by -log2e in smem.
// 2 vertical pixels/thread (30 site-loads serve 50 taps), packed f32x2 math.
// R6: 32x16 tiles, 256-thr blocks, 4 CTAs/SM -> finer wave granularity
// (same 32 warps/SM and 64-reg cap as the 21.0us R3 kernel).

#define BATCH 8
#define NX 256
#define NY 256
#define TILEX 32            // columns (ny)
#define TILEY 16            // rows (nx)
#define HALO 2
#define SMX (TILEX + 2 * HALO)   // 36
#define SMY (TILEY + 2 * HALO)   // 20
#define L2E 1.4426950408889634f

typedef unsigned long long u64;

__device__ __forceinline__ u64 fma2(u64 a, u64 b, u64 c) {
    u64 d; asm("fma.rn.f32x2 %0,%1,%2,%3;" : "=l"(d) : "l"(a), "l"(b), "l"(c)); return d;
}
__device__ __forceinline__ u64 mul2(u64 a, u64 b) {
    u64 d; asm("mul.rn.f32x2 %0,%1,%2;" : "=l"(d) : "l"(a), "l"(b)); return d;
}
__device__ __forceinline__ u64 pack2(float lo, float hi) {
    u64 d; asm("mov.b64 %0,{%1,%2};" : "=l"(d) : "f"(lo), "f"(hi)); return d;
}
__device__ __forceinline__ float hadd2(u64 a) {
    float lo, hi; asm("mov.b64 {%0,%1},%2;" : "=f"(lo), "=f"(hi) : "l"(a));
    return lo + hi;
}
__device__ __forceinline__ float ex2f(float x) {
    float r; asm("ex2.approx.ftz.f32 %0,%1;" : "=f"(r) : "f"(x)); return r;
}
__device__ __forceinline__ int refl(int p, int n) {
    if (p < 0) p = -p;
    if (p >= n) p = 2 * n - 2 - p;
    return p;
}

__global__ __launch_bounds__(256, 4)
void nlm_kernel(const float* __restrict__ x, float* __restrict__ out) {
    __shared__ ulonglong2 sm0[SMY][SMX];   // ch 0-3
    __shared__ ulonglong2 sm1[SMY][SMX];   // ch 4-7
    __shared__ float      snl[SMY][SMX];   // -log2e * ||v||^2

    const int b   = blockIdx.z;
    const int ti0 = blockIdx.y * TILEY;
    const int tj0 = blockIdx.x * TILEX;
    const int tid = threadIdx.y * 32 + threadIdx.x;

    const float* xb = x + (size_t)b * NX * NY * 8;

    // Halo load: 720 sites / 256 threads.
    for (int p = tid; p < SMY * SMX; p += 256) {
        int r = p / SMX;
        int c = p - r * SMX;
        int gi = refl(ti0 + r - HALO, NX);
        int gj = refl(tj0 + c - HALO, NY);
        const float4* src = reinterpret_cast<const float4*>(
            xb + ((size_t)gi * NY + gj) * 8);
        float4 v0 = src[0];
        float4 v1 = src[1];
        *reinterpret_cast<float4*>(&sm0[r][c]) = v0;
        *reinterpret_cast<float4*>(&sm1[r][c]) = v1;
        float nrm = v0.x * v0.x + v0.y * v0.y + v0.z * v0.z + v0.w * v0.w
                  + v1.x * v1.x + v1.y * v1.y + v1.z * v1.z + v1.w * v1.w;
        snl[r][c] = -L2E * nrm;
    }
    __syncthreads();

    // Two vertically adjacent pixels per thread.
    const int y0  = 2 * threadIdx.y;           // tile-local row of pixel0
    const int li0 = y0 + HALO;
    const int lj  = threadIdx.x + HALO;

    const ulonglong2 C00 = sm0[li0][lj];
    const ulonglong2 C01 = sm1[li0][lj];
    const float      pc0 = snl[li0][lj];
    const ulonglong2 C10 = sm0[li0 + 1][lj];
    const ulonglong2 C11 = sm1[li0 + 1][lj];
    const float      pc1 = snl[li0 + 1][lj];

    u64 p0a = 0, p0b = 0, p0c = 0, p0d = 0;
    u64 p1a = 0, p1b = 0, p1c = 0, p1d = 0;
    float ws0 = 0.f, ws1 = 0.f;

    // Window rows r = 0..5 map to smem rows y0 + r.
    // pixel0 uses r in [0,4] (di = r-2); pixel1 uses r in [1,5] (di = r-3).
#pragma unroll
    for (int r = 0; r < 6; r++) {
#pragma unroll
        for (int dj = -HALO; dj <= HALO; dj++) {
            const int sr = y0 + r;
            const ulonglong2 N0 = sm0[sr][lj + dj];
            const ulonglong2 N1 = sm1[sr][lj + dj];
            const float ns = snl[sr][lj + dj];

            if (r <= 4) {
                const int di = r - 2;
                const float cg = -L2E * (0.5f * (float)(di * di + dj * dj));
                u64 dp = mul2(C00.x, N0.x);
                dp = fma2(C00.y, N0.y, dp);
                dp = fma2(C01.x, N1.x, dp);
                dp = fma2(C01.y, N1.y, dp);
                float e = fmaf(2.0f * L2E, hadd2(dp), pc0 + (ns + cg));
                const float w = ex2f(e);
                const u64 w2 = pack2(w, w);
                p0a = fma2(w2, N0.x, p0a);
                p0b = fma2(w2, N0.y, p0b);
                p0c = fma2(w2, N1.x, p0c);
                p0d = fma2(w2, N1.y, p0d);
                ws0 += w;
            }
            if (r >= 1) {
                const int di = r - 3;
                const float cg = -L2E * (0.5f * (float)(di * di + dj * dj));
                u64 dp = mul2(C10.x, N0.x);
                dp = fma2(C10.y, N0.y, dp);
                dp = fma2(C11.x, N1.x, dp);
                dp = fma2(C11.y, N1.y, dp);
                float e = fmaf(2.0f * L2E, hadd2(dp), pc1 + (ns + cg));
                const float w = ex2f(e);
                const u64 w2 = pack2(w, w);
                p1a = fma2(w2, N0.x, p1a);
                p1b = fma2(w2, N0.y, p1b);
                p1c = fma2(w2, N1.x, p1c);
                p1d = fma2(w2, N1.y, p1d);
                ws1 += w;
            }
        }
    }

    const int gi0 = ti0 + y0;
    const int gj  = tj0 + threadIdx.x;

    {
        const float inv = __fdividef(1.f, ws0);
        const u64 inv2 = pack2(inv, inv);
        ulonglong2 r0, r1;
        r0.x = mul2(p0a, inv2); r0.y = mul2(p0b, inv2);
        r1.x = mul2(p0c, inv2); r1.y = mul2(p0d, inv2);
        ulonglong2* dst = reinterpret_cast<ulonglong2*>(
            out + (((size_t)b * NX + gi0) * NY + gj) * 8);
        dst[0] = r0; dst[1] = r1;
    }
    {
        const float inv = __fdividef(1.f, ws1);
        const u64 inv2 = pack2(inv, inv);
        ulonglong2 r0, r1;
        r0.x = mul2(p1a, inv2); r0.y = mul2(p1b, inv2);
        r1.x = mul2(p1c, inv2); r1.y = mul2(p1d, inv2);
        ulonglong2* dst = reinterpret_cast<ulonglong2*>(
            out + (((size_t)b * NX + gi0 + 1) * NY + gj) * 8);
        dst[0] = r0; dst[1] = r1;
    }
}

extern "C" void kernel_launch(void* const* d_in, const int* in_sizes, int n_in,
                              void* d_out, int out_size) {
    const float* x = (const float*)d_in[0];
    float* out = (float*)d_out;
    dim3 block(32, 8, 1);
    dim3 grid(NY / TILEX, NX / TILEY, BATCH);  // (8, 16, 8) = 1024 CTAs
    nlm_kernel<<<grid, block>>>(x, out);
}

// round 7
// speedup vs baseline: 1.1484x; 1.0584x over previous
#include <cuda_runtime.h>
#include <cstdint>

// NonLocalMeansSmoothing: x [8,256,256,8] fp32 -> same. K=5, sigma=1, h=1.
// w ∝ exp(-(||c-n||^2 + 0.5*(di^2+dj^2)))  (gaussian global norm cancels)
// ||c-n||^2 = ||c||^2 + ||n||^2 - 2 c·n; norms pre-scaled by -log2e in smem;
// centers pre-scaled by 2*log2e so the packed dot yields the exponent term
// directly. 2 vertical pixels/thread; explicit 1-deep software pipeline on
// the 30 site loads to hide LDS latency. R3 shape: 512 thr, 32x32 tile,
// 2 CTAs/SM, 64-reg cap.

#define BATCH 8
#define NX 256
#define NY 256
#define TILE 32
#define HALO 2
#define SMW (TILE + 2 * HALO)   // 36
#define L2E 1.4426950408889634f

typedef unsigned long long u64;

__device__ __forceinline__ u64 fma2(u64 a, u64 b, u64 c) {
    u64 d; asm("fma.rn.f32x2 %0,%1,%2,%3;" : "=l"(d) : "l"(a), "l"(b), "l"(c)); return d;
}
__device__ __forceinline__ u64 mul2(u64 a, u64 b) {
    u64 d; asm("mul.rn.f32x2 %0,%1,%2;" : "=l"(d) : "l"(a), "l"(b)); return d;
}
__device__ __forceinline__ u64 pack2(float lo, float hi) {
    u64 d; asm("mov.b64 %0,{%1,%2};" : "=l"(d) : "f"(lo), "f"(hi)); return d;
}
__device__ __forceinline__ float hadd2(u64 a) {
    float lo, hi; asm("mov.b64 {%0,%1},%2;" : "=f"(lo), "=f"(hi) : "l"(a));
    return lo + hi;
}
__device__ __forceinline__ float ex2f(float x) {
    float r; asm("ex2.approx.ftz.f32 %0,%1;" : "=f"(r) : "f"(x)); return r;
}
__device__ __forceinline__ int refl(int p, int n) {
    if (p < 0) p = -p;
    if (p >= n) p = 2 * n - 2 - p;
    return p;
}

__global__ __launch_bounds__(512, 2)
void nlm_kernel(const float* __restrict__ x, float* __restrict__ out) {
    __shared__ ulonglong2 sm0[SMW][SMW];   // ch 0-3
    __shared__ ulonglong2 sm1[SMW][SMW];   // ch 4-7
    __shared__ float      snl[SMW][SMW];   // -log2e * ||v||^2

    const int b   = blockIdx.z;
    const int ti0 = blockIdx.y * TILE;
    const int tj0 = blockIdx.x * TILE;
    const int tid = threadIdx.y * 32 + threadIdx.x;

    const float* xb = x + (size_t)b * NX * NY * 8;

    // Halo load: 1296 sites / 512 threads.
    for (int p = tid; p < SMW * SMW; p += 512) {
        int r = p / SMW;
        int c = p - r * SMW;
        int gi = refl(ti0 + r - HALO, NX);
        int gj = refl(tj0 + c - HALO, NY);
        const float4* src = reinterpret_cast<const float4*>(
            xb + ((size_t)gi * NY + gj) * 8);
        float4 v0 = src[0];
        float4 v1 = src[1];
        *reinterpret_cast<float4*>(&sm0[r][c]) = v0;
        *reinterpret_cast<float4*>(&sm1[r][c]) = v1;
        float nrm = v0.x * v0.x + v0.y * v0.y + v0.z * v0.z + v0.w * v0.w
                  + v1.x * v1.x + v1.y * v1.y + v1.z * v1.z + v1.w * v1.w;
        snl[r][c] = -L2E * nrm;
    }
    __syncthreads();

    // Two vertically adjacent pixels per thread.
    const int y0  = 2 * threadIdx.y;           // tile-local row of pixel0
    const int li0 = y0 + HALO;
    const int lj  = threadIdx.x + HALO;

    // Centers pre-scaled by 2*log2e: packed dot then directly contributes
    // 2*log2e*(c.n) to the exponent.
    const u64 s2 = pack2(2.0f * L2E, 2.0f * L2E);
    u64 C00x, C00y, C01x, C01y, C10x, C10y, C11x, C11y;
    {
        ulonglong2 a = sm0[li0][lj], c2 = sm1[li0][lj];
        C00x = mul2(s2, a.x);  C00y = mul2(s2, a.y);
        C01x = mul2(s2, c2.x); C01y = mul2(s2, c2.y);
        ulonglong2 a1 = sm0[li0 + 1][lj], c3 = sm1[li0 + 1][lj];
        C10x = mul2(s2, a1.x);  C10y = mul2(s2, a1.y);
        C11x = mul2(s2, c3.x);  C11y = mul2(s2, c3.y);
    }
    const float pc0 = snl[li0][lj];        // -log2e*||c0||^2
    const float pc1 = snl[li0 + 1][lj];

    u64 p0a = 0, p0b = 0, p0c = 0, p0d = 0;
    u64 p1a = 0, p1b = 0, p1c = 0, p1d = 0;
    float ws0 = 0.f, ws1 = 0.f;

    // 30 sites: m -> (r = m/5, dj = m%5 - 2); smem row y0+r, col lj+dj.
    // pixel0 taps r in [0,4] (di=r-2); pixel1 taps r in [1,5] (di=r-3).
    ulonglong2 N0 = sm0[y0][lj - 2];
    ulonglong2 N1 = sm1[y0][lj - 2];
    float      ns = snl[y0][lj - 2];

#pragma unroll
    for (int m = 0; m < 30; m++) {
        const int r  = m / 5;
        const int dj = m % 5 - 2;

        // Prefetch next site (1-deep pipeline).
        ulonglong2 nN0, nN1; float nns;
        if (m < 29) {
            const int mr  = (m + 1) / 5;
            const int mdj = (m + 1) % 5 - 2;
            nN0 = sm0[y0 + mr][lj + mdj];
            nN1 = sm1[y0 + mr][lj + mdj];
            nns = snl[y0 + mr][lj + mdj];
        }

        if (r <= 4) {
            const int di = r - 2;
            const float cg = -L2E * (0.5f * (float)(di * di + dj * dj));
            u64 dp = mul2(C00x, N0.x);
            dp = fma2(C00y, N0.y, dp);
            dp = fma2(C01x, N1.x, dp);
            dp = fma2(C01y, N1.y, dp);
            const float w = ex2f(hadd2(dp) + ((pc0 + cg) + ns));
            const u64 w2 = pack2(w, w);
            p0a = fma2(w2, N0.x, p0a);
            p0b = fma2(w2, N0.y, p0b);
            p0c = fma2(w2, N1.x, p0c);
            p0d = fma2(w2, N1.y, p0d);
            ws0 += w;
        }
        if (r >= 1) {
            const int di = r - 3;
            const float cg = -L2E * (0.5f * (float)(di * di + dj * dj));
            u64 dp = mul2(C10x, N0.x);
            dp = fma2(C10y, N0.y, dp);
            dp = fma2(C11x, N1.x, dp);
            dp = fma2(C11y, N1.y, dp);
            const float w = ex2f(hadd2(dp) + ((pc1 + cg) + ns));
            const u64 w2 = pack2(w, w);
            p1a = fma2(w2, N0.x, p1a);
            p1b = fma2(w2, N0.y, p1b);
            p1c = fma2(w2, N1.x, p1c);
            p1d = fma2(w2, N1.y, p1d);
            ws1 += w;
        }

        N0 = nN0; N1 = nN1; ns = nns;
    }

    const int gi0 = ti0 + y0;
    const int gj  = tj0 + threadIdx.x;

    {
        const float inv = __fdividef(1.f, ws0);
        const u64 inv2 = pack2(inv, inv);
        ulonglong2 r0, r1;
        r0.x = mul2(p0a, inv2); r0.y = mul2(p0b, inv2);
        r1.x = mul2(p0c, inv2); r1.y = mul2(p0d, inv2);
        ulonglong2* dst = reinterpret_cast<ulonglong2*>(
            out + (((size_t)b * NX + gi0) * NY + gj) * 8);
        dst[0] = r0; dst[1] = r1;
    }
    {
        const float inv = __fdividef(1.f, ws1);
        const u64 inv2 = pack2(inv, inv);
        ulonglong2 r0, r1;
        r0.x = mul2(p1a, inv2); r0.y = mul2(p1b, inv2);
        r1.x = mul2(p1c, inv2); r1.y = mul2(p1d, inv2);
        ulonglong2* dst = reinterpret_cast<ulonglong2*>(
            out + (((size_t)b * NX + gi0 + 1) * NY + gj) * 8);
        dst[0] = r0; dst[1] = r1;
    }
}

extern "C" void kernel_launch(void* const* d_in, const int* in_sizes, int n_in,
                              void* d_out, int out_size) {
    const float* x = (const float*)d_in[0];
    float* out = (float*)d_out;
    dim3 block(32, 16, 1);
    dim3 grid(NY / TILE, NX / TILE, BATCH);  // (8, 8, 8)
    nlm_kernel<<<grid, block>>>(x, out);
}